// round 9
// baseline (speedup 1.0000x reference)
#include <cuda_runtime.h>
#include <cuda_fp16.h>
#include <math.h>
#include <stdint.h>

#define NB 32768
#define HD 512
#define DV 256
#define NP 512
#define RHO_MAXF 9.0f
#define DELTAF 0.001f
#define EPSF 1e-8f
#define PIF 3.14159265358979f

// ---------------- scratch (__device__ globals: no allocations allowed) ----------------
__device__ __half g_hEnt[NB*HD];
__device__ __half g_hRel[NB*HD];
__device__ __half g_hLab[NB*HD];
__device__ __half g_hH0[NB*HD];
__device__ __half g_hH1[NB*HD];
__device__ __half g_hH2[NB*HD];
__device__ __half g_hEh[NB*HD];
__device__ __half g_hEr[NB*HD];
__device__ __half g_hEt[NB*HD];
__device__ __half g_hW1[HD*HD];
__device__ __half g_hW2[HD*HD];
__device__ __half g_hWv[DV*HD];
__device__ __half g_hWt[NP*HD];
__device__ float g_thT[NP*NB];
__device__ float g_uhT[DV*NB];
__device__ float g_utT[DV*NB];
__device__ float g_urT[DV*NB];
__device__ float g_reh[NB];
__device__ float g_rrr[NB];
__device__ float g_ret[NB];
__device__ float g_invh[NB];
__device__ float g_invt[NB];

__device__ __forceinline__ float softplusf(float x) {
    return (x > 20.f) ? x : log1pf(expf(x));
}

__device__ __forceinline__ float fast_tanh(float x) {
    float y;
    asm("tanh.approx.f32 %0, %1;" : "=f"(y) : "f"(x));
    return y;
}

#define CP_ASYNC16(dst, src) \
    asm volatile("cp.async.cg.shared.global [%0], [%1], 16;" :: "r"(dst), "l"(src))
#define CP_COMMIT() asm volatile("cp.async.commit_group;" ::: "memory")
#define CP_WAITG2() asm volatile("cp.async.wait_group 2;" ::: "memory")

#define LDSM4(r0, r1, r2, r3, addr) \
    asm volatile("ldmatrix.sync.aligned.m8n8.x4.shared.b16 {%0,%1,%2,%3}, [%4];" \
                 : "=r"(r0), "=r"(r1), "=r"(r2), "=r"(r3) : "r"(addr))

__device__ __forceinline__ uint32_t smem_u32(const void* p) {
    uint32_t a;
    asm("{ .reg .u64 t; cvta.to.shared.u64 t, %1; cvt.u32.u64 %0, t; }" : "=r"(a) : "l"(p));
    return a;
}

// ---------------- fp32 -> fp16 conversions -------------------------------------------
__global__ void cvt3_f2h(const float* __restrict__ s0, const float* __restrict__ s1,
                         const float* __restrict__ s2,
                         __half* __restrict__ d0, __half* __restrict__ d1,
                         __half* __restrict__ d2)
{
    const float* s = (blockIdx.y == 0) ? s0 : (blockIdx.y == 1) ? s1 : s2;
    __half* d = (blockIdx.y == 0) ? d0 : (blockIdx.y == 1) ? d1 : d2;
    const int i = (blockIdx.x * blockDim.x + threadIdx.x) * 8;
    float4 a = *(const float4*)&s[i];
    float4 b = *(const float4*)&s[i + 4];
    __half2 h0 = __floats2half2_rn(a.x, a.y);
    __half2 h1 = __floats2half2_rn(a.z, a.w);
    __half2 h2 = __floats2half2_rn(b.x, b.y);
    __half2 h3 = __floats2half2_rn(b.z, b.w);
    uint4 o;
    o.x = *(uint32_t*)&h0; o.y = *(uint32_t*)&h1;
    o.z = *(uint32_t*)&h2; o.w = *(uint32_t*)&h3;
    *(uint4*)&d[i] = o;
}

__global__ void cvt_f2h(const float* __restrict__ src, __half* __restrict__ dst, int n)
{
    const int i = (blockIdx.x * blockDim.x + threadIdx.x) * 8;
    if (i >= n) return;
    float4 a = *(const float4*)&src[i];
    float4 b = *(const float4*)&src[i + 4];
    __half2 h0 = __floats2half2_rn(a.x, a.y);
    __half2 h1 = __floats2half2_rn(a.z, a.w);
    __half2 h2 = __floats2half2_rn(b.x, b.y);
    __half2 h3 = __floats2half2_rn(b.z, b.w);
    uint4 o;
    o.x = *(uint32_t*)&h0; o.y = *(uint32_t*)&h1;
    o.z = *(uint32_t*)&h2; o.w = *(uint32_t*)&h3;
    *(uint4*)&dst[i] = o;
}

// ---------------- FP16 tensor-core NT GEMM (m16n8k16 + ldmatrix, 4-stage, 1 sync) ----
// C[M,N] = A[M,512] * W[N,512]^T + bias, fp32 accumulate.
// Block 128M x 128N, 8 warps (4m x 2n), warp tile 32x64, KTILE=32, 4-stage cp.async,
// single __syncthreads per mainloop iteration. Smem stride 20 words.
// mode bits: 1=relu, 2=+residual(fp32 R), 8=store fp16 Ch,
//            16=transposed fp32 store to C (ldim NB), 32=apply pi*tanh (with 16)
#define SMS 20
#define KDIM 512
#define KT 32
#define NKT (KDIM / KT)            // 16
#define SA_WORDS (128 * SMS)       // 2560
#define STG_WORDS (2 * SA_WORDS)   // 5120
#define STG_BYTES (STG_WORDS * 4)  // 20480
#define GEMM_SMEM_BYTES (4 * STG_BYTES)   // 81920

__global__ __launch_bounds__(256, 2)
void gemm_h(const __half* __restrict__ A0, const __half* __restrict__ A1,
            const __half* __restrict__ A2,
            const __half* __restrict__ W, const float* __restrict__ bias,
            const float* __restrict__ R0, const float* __restrict__ R1,
            const float* __restrict__ R2,
            float* __restrict__ C0, float* __restrict__ C1, float* __restrict__ C2,
            __half* __restrict__ Ch0, __half* __restrict__ Ch1, __half* __restrict__ Ch2,
            int N, int mode)
{
    extern __shared__ __align__(16) uint32_t smem[];
    const int tid = threadIdx.x, wid = tid >> 5, lane = tid & 31;
    const int g = lane >> 2, tg = lane & 3;
    const int z = blockIdx.z;
    const __half* A = (z == 0) ? A0 : (z == 1) ? A1 : A2;
    const float*  R = (z == 0) ? R0 : (z == 1) ? R1 : R2;
    float*        C = (z == 0) ? C0 : (z == 1) ? C1 : C2;
    __half*      Ch = (z == 0) ? Ch0 : (z == 1) ? Ch1 : Ch2;
    const int m0 = blockIdx.y * 128;
    const int n0 = blockIdx.x * 128;
    const int moff = (wid & 3) * 32;
    const int noff = (wid >> 2) * 64;
    const __half* Ag = A + (size_t)m0 * KDIM;
    const __half* Bg = W + (size_t)n0 * KDIM;

    const uint32_t sbase = smem_u32(smem);

    // ldmatrix per-lane addressing
    const int lrow8 = ((lane >> 3) & 1) * 8 + (lane & 7);
    const int lk4   = (lane >> 4) * 4;
    uint32_t aoff[2], boff[4];
    #pragma unroll
    for (int mt = 0; mt < 2; mt++)
        aoff[mt] = ((moff + mt * 16 + lrow8) * SMS + lk4) * 4;
    #pragma unroll
    for (int ntp = 0; ntp < 4; ntp++)
        boff[ntp] = ((noff + ntp * 16 + lrow8) * SMS + lk4) * 4;

    float acc[2][8][4];
    #pragma unroll
    for (int mt = 0; mt < 2; mt++)
        #pragma unroll
        for (int nt = 0; nt < 8; nt++)
            #pragma unroll
            for (int q = 0; q < 4; q++) acc[mt][nt][q] = 0.f;

    #define FILL_STAGE(stg, k0)                                                      \
    do {                                                                             \
        const uint32_t wA = sbase + (stg) * STG_BYTES;                               \
        const uint32_t wB = wA + SA_WORDS * 4;                                       \
        _Pragma("unroll")                                                            \
        for (int p = 0; p < 2; p++) {                                                \
            const int c = tid + 256 * p;                                             \
            const int row = c >> 2;                                                  \
            CP_ASYNC16(wA + (row * SMS + (c & 3) * 4) * 4,                           \
                       &Ag[(size_t)row * KDIM + (k0) + (c & 3) * 8]);                \
            CP_ASYNC16(wB + (row * SMS + (c & 3) * 4) * 4,                           \
                       &Bg[(size_t)row * KDIM + (k0) + (c & 3) * 8]);                \
        }                                                                            \
    } while (0)

    FILL_STAGE(0, 0);      CP_COMMIT();
    FILL_STAGE(1, KT);     CP_COMMIT();
    FILL_STAGE(2, 2 * KT); CP_COMMIT();

    for (int t = 0; t < NKT; t++) {
        CP_WAITG2();              // chunk t resident
        __syncthreads();          // all warps done with compute(t-1): stage (t+3)&3 free
        if (t + 3 < NKT) { FILL_STAGE((t + 3) & 3, (t + 3) * KT); }
        CP_COMMIT();              // uniform group counting (empty commit ok)

        const uint32_t Ab = sbase + (t & 3) * STG_BYTES;
        const uint32_t Bb = Ab + SA_WORDS * 4;

        #pragma unroll
        for (int ks = 0; ks < 2; ks++) {
            const uint32_t kb4 = ks * 32;
            uint32_t af[2][4], bf[8][2];
            #pragma unroll
            for (int mt = 0; mt < 2; mt++)
                LDSM4(af[mt][0], af[mt][1], af[mt][2], af[mt][3], Ab + aoff[mt] + kb4);
            #pragma unroll
            for (int ntp = 0; ntp < 4; ntp++)
                LDSM4(bf[2*ntp][0], bf[2*ntp+1][0], bf[2*ntp][1], bf[2*ntp+1][1],
                      Bb + boff[ntp] + kb4);
            #pragma unroll
            for (int mt = 0; mt < 2; mt++)
                #pragma unroll
                for (int nt = 0; nt < 8; nt++) {
                    asm volatile(
                        "mma.sync.aligned.m16n8k16.row.col.f32.f16.f16.f32 "
                        "{%0,%1,%2,%3}, {%4,%5,%6,%7}, {%8,%9}, {%0,%1,%2,%3};"
                        : "+f"(acc[mt][nt][0]), "+f"(acc[mt][nt][1]),
                          "+f"(acc[mt][nt][2]), "+f"(acc[mt][nt][3])
                        : "r"(af[mt][0]), "r"(af[mt][1]), "r"(af[mt][2]), "r"(af[mt][3]),
                          "r"(bf[nt][0]), "r"(bf[nt][1]));
                }
        }
    }

    if (mode & 16) {
        // ---- transposed epilogue: stage 64 cols at a time through pipeline smem ----
        float* st = (float*)smem;     // tile[128][65]
        #pragma unroll
        for (int half = 0; half < 2; half++) {
            __syncthreads();
            if ((wid >> 2) == half) {
                #pragma unroll
                for (int mt = 0; mt < 2; mt++)
                    #pragma unroll
                    for (int nt = 0; nt < 8; nt++) {
                        const int cl = nt * 8 + 2 * tg;
                        const int r0 = moff + mt * 16 + g;
                        st[r0 * 65 + cl]           = acc[mt][nt][0];
                        st[r0 * 65 + cl + 1]       = acc[mt][nt][1];
                        st[(r0 + 8) * 65 + cl]     = acc[mt][nt][2];
                        st[(r0 + 8) * 65 + cl + 1] = acc[mt][nt][3];
                    }
            }
            __syncthreads();
            #pragma unroll
            for (int i = 0; i < 32; i++) {
                const int idx = tid + 256 * i;
                const int c = idx >> 7;           // 0..63
                const int b = idx & 127;
                float v = st[b * 65 + c] + bias[n0 + half * 64 + c];
                if (mode & 32) v = PIF * fast_tanh(v);
                C[(size_t)(n0 + half * 64 + c) * NB + m0 + b] = v;
            }
        }
        return;
    }

    // ---- standard epilogue ----
    #pragma unroll
    for (int mt = 0; mt < 2; mt++) {
        #pragma unroll
        for (int nt = 0; nt < 8; nt++) {
            const int n = n0 + noff + nt * 8 + 2 * tg;
            const int ra = m0 + moff + mt * 16 + g;
            const int rb = ra + 8;
            float bx = bias[n], by = bias[n + 1];
            float2 v0 = make_float2(acc[mt][nt][0] + bx, acc[mt][nt][1] + by);
            float2 v1 = make_float2(acc[mt][nt][2] + bx, acc[mt][nt][3] + by);
            if (mode & 1) {
                v0.x = fmaxf(v0.x, 0.f); v0.y = fmaxf(v0.y, 0.f);
                v1.x = fmaxf(v1.x, 0.f); v1.y = fmaxf(v1.y, 0.f);
            }
            if (mode & 2) {
                float2 r0v = *(const float2*)&R[(size_t)ra * N + n];
                float2 r1v = *(const float2*)&R[(size_t)rb * N + n];
                v0.x += r0v.x; v0.y += r0v.y;
                v1.x += r1v.x; v1.y += r1v.y;
            }
            if (mode & 8) {
                __half2 h0 = __floats2half2_rn(v0.x, v0.y);
                __half2 h1 = __floats2half2_rn(v1.x, v1.y);
                *(__half2*)&Ch[(size_t)ra * N + n] = h0;
                *(__half2*)&Ch[(size_t)rb * N + n] = h1;
            }
        }
    }
}

// ---------------- column norms of transposed u: inv[b] = 1/(||u[:,b]||+eps) ----------
__global__ void colnorm2(const float* __restrict__ uhT, const float* __restrict__ utT,
                         float* __restrict__ invh, float* __restrict__ invt)
{
    const float* u = (blockIdx.y == 0) ? uhT : utT;
    float* o = (blockIdx.y == 0) ? invh : invt;
    const int b = blockIdx.x * blockDim.x + threadIdx.x;
    float s = 0.f;
    #pragma unroll 8
    for (int c = 0; c < DV; c++) {
        float v = u[(size_t)c * NB + b];
        s = fmaf(v, v, s);
    }
    o[b] = 1.f / (sqrtf(s) + EPSF);
}

// ---------------- three N=1 GEMVs on fp16 E: re_h, rr_r, re_t ------------------------
__global__ void gemv3h(const __half* __restrict__ Eh, const __half* __restrict__ Er,
                       const __half* __restrict__ Et,
                       const float* __restrict__ Wre, const float* __restrict__ bre,
                       const float* __restrict__ Wrr, const float* __restrict__ brr,
                       float* __restrict__ reh, float* __restrict__ rrr, float* __restrict__ ret)
{
    const int warp = (blockIdx.x * blockDim.x + threadIdx.x) >> 5;
    const int lane = threadIdx.x & 31;
    if (warp >= NB) return;
    const __half* eh = Eh + (size_t)warp * HD;
    const __half* er = Er + (size_t)warp * HD;
    const __half* et = Et + (size_t)warp * HD;
    float s1 = 0.f, s2 = 0.f, s3 = 0.f;
    #pragma unroll
    for (int k = lane * 8; k < HD; k += 256) {
        uint4 a = *(const uint4*)&eh[k];
        uint4 b = *(const uint4*)&er[k];
        uint4 c = *(const uint4*)&et[k];
        #pragma unroll
        for (int j = 0; j < 4; j++) {
            float2 ea = __half22float2(*(const __half2*)((const uint32_t*)&a + j));
            float2 eb = __half22float2(*(const __half2*)((const uint32_t*)&b + j));
            float2 ec = __half22float2(*(const __half2*)((const uint32_t*)&c + j));
            float2 wre = *(const float2*)&Wre[k + 2 * j];
            float2 wrr = *(const float2*)&Wrr[k + 2 * j];
            s1 = fmaf(ea.x, wre.x, fmaf(ea.y, wre.y, s1));
            s2 = fmaf(eb.x, wrr.x, fmaf(eb.y, wrr.y, s2));
            s3 = fmaf(ec.x, wre.x, fmaf(ec.y, wre.y, s3));
        }
    }
    #pragma unroll
    for (int o = 16; o > 0; o >>= 1) {
        s1 += __shfl_down_sync(0xffffffffu, s1, o);
        s2 += __shfl_down_sync(0xffffffffu, s2, o);
        s3 += __shfl_down_sync(0xffffffffu, s3, o);
    }
    if (lane == 0) {
        reh[warp] = s1 + bre[0];
        rrr[warp] = s2 + brr[0];
        ret[warp] = s3 + bre[0];
    }
}

// ---------------- fused rotation + slerp + score (inv-norm applied at load) ----------
__global__ void rot_score(
    const float* __restrict__ uhT, const float* __restrict__ utT,
    const float* __restrict__ thT, float* __restrict__ urT,
    const float* __restrict__ invh, const float* __restrict__ invt,
    const float* __restrict__ sim,
    const float* __restrict__ reh, const float* __restrict__ rrr, const float* __restrict__ ret,
    const float* __restrict__ ga_rho, const float* __restrict__ gb_rho,
    const float* __restrict__ ga_phi, const float* __restrict__ gb_phi,
    float* __restrict__ out)
{
    const int b = blockIdx.x * blockDim.x + threadIdx.x;
    if (b >= NB) return;
    const float ih = invh[b], it = invt[b];

    float cur = uhT[b] * ih;
    float u0w = 0.f;
    #pragma unroll 4
    for (int i = 0; i < 255; i++) {
        float s, c; __sincosf(thT[(size_t)i * NB + b], &s, &c);
        float nxt = uhT[(size_t)(i + 1) * NB + b] * ih;
        float wi = c * cur - s * nxt;
        urT[(size_t)i * NB + b] = wi;
        if (i == 0) u0w = wi;
        cur = s * cur + c * nxt;
    }
    {
        float s, c; __sincosf(thT[(size_t)255 * NB + b], &s, &c);
        float w255 = c * cur - s * u0w;
        float w0   = s * cur + c * u0w;
        urT[(size_t)255 * NB + b] = w255;
        urT[b] = w0;
    }

    float dhr = 0.f, dht = 0.f, drt = 0.f, ssq = 0.f;
    const float uh0 = uhT[b] * ih, ut0 = utT[b] * it;
    cur = urT[b];
    float w0sav = 0.f;
    #pragma unroll 4
    for (int i = 0; i < 255; i++) {
        float s, c; __sincosf(thT[(size_t)(256 + i) * NB + b], &s, &c);
        float nxt = urT[(size_t)(i + 1) * NB + b];
        float wi = c * cur - s * nxt;
        cur = s * cur + c * nxt;
        if (i == 0) {
            w0sav = wi;
        } else {
            float uh = uhT[(size_t)i * NB + b] * ih;
            float ut = utT[(size_t)i * NB + b] * it;
            ssq += wi * wi; dhr += wi * uh; drt += wi * ut; dht += uh * ut;
        }
    }
    float w255f, w0f;
    {
        float s, c; __sincosf(thT[(size_t)511 * NB + b], &s, &c);
        w255f = c * cur - s * w0sav;
        w0f   = s * cur + c * w0sav;
    }
    {
        float uh255 = uhT[(size_t)255 * NB + b] * ih, ut255 = utT[(size_t)255 * NB + b] * it;
        ssq += w255f * w255f + w0f * w0f;
        dhr += w255f * uh255 + w0f * uh0;
        drt += w255f * ut255 + w0f * ut0;
        dht += uh255 * ut255 + uh0 * ut0;
    }

    float nr = sqrtf(ssq);
    float inv_rot = 1.f / (nr + EPSF);
    float dhr_n = dhr * inv_rot;
    float dotc = fminf(fmaxf(dhr_n, -1.f + EPSF), 1.f - EPSF);
    float omega = acosf(dotc);
    float sin_om = sinf(omega);
    float sv = sim[b];
    float grho = 1.f / (1.f + expf(-(ga_rho[0] * sv + gb_rho[0])));
    float gphi = 1.f / (1.f + expf(-(ga_phi[0] * sv + gb_phi[0])));
    float ca, cb;
    if (omega > DELTAF) {
        float iso = 1.f / (sin_om + EPSF);
        ca = sinf((1.f - gphi) * omega) * iso;
        cb = sinf(gphi * omega) * iso;
    } else {
        ca = 1.f - gphi; cb = gphi;
    }
    float nrn = nr * inv_rot;
    float np2 = ca * ca + cb * cb * nrn * nrn + 2.f * ca * cb * dhr_n;
    float npv = sqrtf(fmaxf(np2, 0.f));
    float inv_np = 1.f / (npv + EPSF);
    float dpt = (ca * dht + cb * drt * inv_rot) * inv_np;

    float rho_h = fminf(softplusf(reh[b]), RHO_MAXF);
    float rho_p = fminf(fmaxf(rho_h + rrr[b] * grho, 0.f), RHO_MAXF);
    float rho_t = fminf(softplusf(ret[b]), RHO_MAXF);
    out[b] = -coshf(rho_p) * coshf(rho_t) + sinhf(rho_p) * sinhf(rho_t) * dpt;
}

// ---------------- launch --------------------------------------------------------------
extern "C" void kernel_launch(void* const* d_in, const int* in_sizes, int n_in,
                              void* d_out, int out_size)
{
    const float* ent  = (const float*)d_in[0];
    const float* rel  = (const float*)d_in[1];
    const float* lab  = (const float*)d_in[2];
    const float* sim  = (const float*)d_in[3];
    const float* Wv   = (const float*)d_in[4];
    const float* bv   = (const float*)d_in[5];
    const float* Wre  = (const float*)d_in[6];
    const float* bre  = (const float*)d_in[7];
    const float* Wrr  = (const float*)d_in[8];
    const float* brr  = (const float*)d_in[9];
    const float* Wt   = (const float*)d_in[10];
    const float* bt   = (const float*)d_in[11];
    const float* ga_rho = (const float*)d_in[12];
    const float* gb_rho = (const float*)d_in[13];
    const float* ga_phi = (const float*)d_in[14];
    const float* gb_phi = (const float*)d_in[15];
    const float* W1   = (const float*)d_in[16];
    const float* b1   = (const float*)d_in[17];
    const float* W2   = (const float*)d_in[18];
    const float* b2   = (const float*)d_in[19];
    float* out = (float*)d_out;

    __half *hEnt, *hRel, *hLab, *hH0, *hH1, *hH2, *hEh, *hEr, *hEt;
    __half *hW1, *hW2, *hWv, *hWt;
    float *thT, *uhT, *utT, *urT, *reh, *rrr, *ret, *invh, *invt;
    cudaGetSymbolAddress((void**)&hEnt, g_hEnt);
    cudaGetSymbolAddress((void**)&hRel, g_hRel);
    cudaGetSymbolAddress((void**)&hLab, g_hLab);
    cudaGetSymbolAddress((void**)&hH0,  g_hH0);
    cudaGetSymbolAddress((void**)&hH1,  g_hH1);
    cudaGetSymbolAddress((void**)&hH2,  g_hH2);
    cudaGetSymbolAddress((void**)&hEh,  g_hEh);
    cudaGetSymbolAddress((void**)&hEr,  g_hEr);
    cudaGetSymbolAddress((void**)&hEt,  g_hEt);
    cudaGetSymbolAddress((void**)&hW1,  g_hW1);
    cudaGetSymbolAddress((void**)&hW2,  g_hW2);
    cudaGetSymbolAddress((void**)&hWv,  g_hWv);
    cudaGetSymbolAddress((void**)&hWt,  g_hWt);
    cudaGetSymbolAddress((void**)&thT,  g_thT);
    cudaGetSymbolAddress((void**)&uhT,  g_uhT);
    cudaGetSymbolAddress((void**)&utT,  g_utT);
    cudaGetSymbolAddress((void**)&urT,  g_urT);
    cudaGetSymbolAddress((void**)&reh,  g_reh);
    cudaGetSymbolAddress((void**)&rrr,  g_rrr);
    cudaGetSymbolAddress((void**)&ret,  g_ret);
    cudaGetSymbolAddress((void**)&invh, g_invh);
    cudaGetSymbolAddress((void**)&invt, g_invt);

    cudaFuncSetAttribute(gemm_h, cudaFuncAttributeMaxDynamicSharedMemorySize,
                         GEMM_SMEM_BYTES);

    // fp32 -> fp16 conversions
    const int BIG = NB * HD;
    cvt3_f2h<<<dim3(BIG / (256 * 8), 3), 256>>>(ent, rel, lab, hEnt, hRel, hLab);
    cvt_f2h<<<(HD * HD) / (256 * 8), 256>>>(W1, hW1, HD * HD);
    cvt_f2h<<<(HD * HD) / (256 * 8), 256>>>(W2, hW2, HD * HD);
    cvt_f2h<<<(DV * HD) / (256 * 8), 256>>>(Wv, hWv, DV * HD);
    cvt_f2h<<<(NP * HD) / (256 * 8), 256>>>(Wt, hWt, NP * HD);

    const dim3 blk(256);
    // layer 1: hH_z = fp16(relu(X_z @ W1^T + b1))            mode 1|8 = 9
    gemm_h<<<dim3(HD/128, NB/128, 3), blk, GEMM_SMEM_BYTES>>>(
        hEnt, hRel, hLab, hW1, b1, nullptr, nullptr, nullptr,
        nullptr, nullptr, nullptr, hH0, hH1, hH2, HD, 9);
    // layer 2: hE_z = fp16(H_z @ W2^T + b2 + X_z)            mode 2|8 = 10
    gemm_h<<<dim3(HD/128, NB/128, 3), blk, GEMM_SMEM_BYTES>>>(
        hH0, hH1, hH2, hW2, b2, ent, rel, lab,
        nullptr, nullptr, nullptr, hEh, hEr, hEt, HD, 10);
    // Wv projections, transposed fp32 out (unnormalized)     mode 16
    gemm_h<<<dim3(DV/128, NB/128, 2), blk, GEMM_SMEM_BYTES>>>(
        hEh, hEt, nullptr, hWv, bv, nullptr, nullptr, nullptr,
        uhT, utT, nullptr, nullptr, nullptr, nullptr, DV, 16);
    // theta logits, transposed + pi*tanh                     mode 16|32 = 48
    gemm_h<<<dim3(NP/128, NB/128, 1), blk, GEMM_SMEM_BYTES>>>(
        hEr, nullptr, nullptr, hWt, bt, nullptr, nullptr, nullptr,
        thT, nullptr, nullptr, nullptr, nullptr, nullptr, NP, 48);

    // column norms of transposed u
    colnorm2<<<dim3(NB / 256, 2), 256>>>(uhT, utT, invh, invt);

    // scalar GEMVs (rho logits / delta_rho) on fp16 E
    gemv3h<<<NB / 8, 256>>>(hEh, hEr, hEt, Wre, bre, Wrr, brr, reh, rrr, ret);

    // fused Givens sweeps + slerp + hyperbolic score
    rot_score<<<NB / 256, 256>>>(uhT, utT, thT, urT, invh, invt, sim, reh, rrr, ret,
                                 ga_rho, gb_rho, ga_phi, gb_phi, out);
    (void)in_sizes; (void)n_in; (void)out_size;
}

// round 10
// speedup vs baseline: 1.5267x; 1.5267x over previous
#include <cuda_runtime.h>
#include <cuda_fp16.h>
#include <math.h>
#include <stdint.h>

#define NB 32768
#define HD 512
#define DV 256
#define NP 512
#define RHO_MAXF 9.0f
#define DELTAF 0.001f
#define EPSF 1e-8f
#define PIF 3.14159265358979f

// ---------------- scratch (__device__ globals: no allocations allowed) ----------------
__device__ __half g_hEnt[NB*HD];
__device__ __half g_hRel[NB*HD];
__device__ __half g_hLab[NB*HD];
__device__ __half g_hH0[NB*HD];
__device__ __half g_hH1[NB*HD];
__device__ __half g_hH2[NB*HD];
__device__ __half g_hEh[NB*HD];
__device__ __half g_hEr[NB*HD];
__device__ __half g_hEt[NB*HD];
__device__ __half g_hW1[HD*HD];
__device__ __half g_hW2[HD*HD];
__device__ __half g_hWv[DV*HD];
__device__ __half g_hWt[NP*HD];
__device__ float g_Vh[NB*DV];
__device__ float g_Vt[NB*DV];
__device__ float g_TH[NB*NP];
__device__ float g_thT[NP*NB];
__device__ float g_uhT[DV*NB];
__device__ float g_utT[DV*NB];
__device__ float g_urT[DV*NB];
__device__ float g_reh[NB];
__device__ float g_rrr[NB];
__device__ float g_ret[NB];

__device__ __forceinline__ float softplusf(float x) {
    return (x > 20.f) ? x : log1pf(expf(x));
}

__device__ __forceinline__ float fast_tanh(float x) {
    float y;
    asm("tanh.approx.f32 %0, %1;" : "=f"(y) : "f"(x));
    return y;
}

#define CP_ASYNC16(dst, src) \
    asm volatile("cp.async.cg.shared.global [%0], [%1], 16;" :: "r"(dst), "l"(src))
#define CP_COMMIT() asm volatile("cp.async.commit_group;" ::: "memory")
#define CP_WAIT2()  asm volatile("cp.async.wait_group 2;" ::: "memory")
#define CP_WAIT1()  asm volatile("cp.async.wait_group 1;" ::: "memory")

#define LDSM4(r0, r1, r2, r3, addr) \
    asm volatile("ldmatrix.sync.aligned.m8n8.x4.shared.b16 {%0,%1,%2,%3}, [%4];" \
                 : "=r"(r0), "=r"(r1), "=r"(r2), "=r"(r3) : "r"(addr))

__device__ __forceinline__ uint32_t smem_u32(const void* p) {
    uint32_t a;
    asm("{ .reg .u64 t; cvta.to.shared.u64 t, %1; cvt.u32.u64 %0, t; }" : "=r"(a) : "l"(p));
    return a;
}

// ---------------- fp32 -> fp16 conversions -------------------------------------------
__global__ void cvt3_f2h(const float* __restrict__ s0, const float* __restrict__ s1,
                         const float* __restrict__ s2,
                         __half* __restrict__ d0, __half* __restrict__ d1,
                         __half* __restrict__ d2)
{
    const float* s = (blockIdx.y == 0) ? s0 : (blockIdx.y == 1) ? s1 : s2;
    __half* d = (blockIdx.y == 0) ? d0 : (blockIdx.y == 1) ? d1 : d2;
    const int i = (blockIdx.x * blockDim.x + threadIdx.x) * 8;
    float4 a = *(const float4*)&s[i];
    float4 b = *(const float4*)&s[i + 4];
    __half2 h0 = __floats2half2_rn(a.x, a.y);
    __half2 h1 = __floats2half2_rn(a.z, a.w);
    __half2 h2 = __floats2half2_rn(b.x, b.y);
    __half2 h3 = __floats2half2_rn(b.z, b.w);
    uint4 o;
    o.x = *(uint32_t*)&h0; o.y = *(uint32_t*)&h1;
    o.z = *(uint32_t*)&h2; o.w = *(uint32_t*)&h3;
    *(uint4*)&d[i] = o;
}

__global__ void cvt_f2h(const float* __restrict__ src, __half* __restrict__ dst, int n)
{
    const int i = (blockIdx.x * blockDim.x + threadIdx.x) * 8;
    if (i >= n) return;
    float4 a = *(const float4*)&src[i];
    float4 b = *(const float4*)&src[i + 4];
    __half2 h0 = __floats2half2_rn(a.x, a.y);
    __half2 h1 = __floats2half2_rn(a.z, a.w);
    __half2 h2 = __floats2half2_rn(b.x, b.y);
    __half2 h3 = __floats2half2_rn(b.z, b.w);
    uint4 o;
    o.x = *(uint32_t*)&h0; o.y = *(uint32_t*)&h1;
    o.z = *(uint32_t*)&h2; o.w = *(uint32_t*)&h3;
    *(uint4*)&dst[i] = o;
}

// ---------------- FP16 tensor-core NT GEMM (m16n8k16 + ldmatrix, 2 CTA/SM) -----------
// C[M,N] = A[M,512] * W[N,512]^T + bias, fp32 accumulate.
// Block 128M x 128N, 8 warps (4m x 2n), warp tile 32x64, KTILE=32 (2 k16 steps),
// 3-stage cp.async, ldmatrix.x4 fragments. Smem stride 20 words.
// mode bits: 1=relu, 2=+residual(fp32), 4=store fp32 C, 8=store fp16 Ch
#define SMS 20
#define KDIM 512
#define KT 32
#define NKT (KDIM / KT)            // 16
#define SA_WORDS (128 * SMS)       // 2560
#define STG_WORDS (2 * SA_WORDS)   // 5120
#define STG_BYTES (STG_WORDS * 4)
#define GEMM_SMEM_BYTES (3 * STG_BYTES)   // 61440

__global__ __launch_bounds__(256, 2)
void gemm_h(const __half* __restrict__ A0, const __half* __restrict__ A1,
            const __half* __restrict__ A2,
            const __half* __restrict__ W, const float* __restrict__ bias,
            const float* __restrict__ R0, const float* __restrict__ R1,
            const float* __restrict__ R2,
            float* __restrict__ C0, float* __restrict__ C1, float* __restrict__ C2,
            __half* __restrict__ Ch0, __half* __restrict__ Ch1, __half* __restrict__ Ch2,
            int N, int mode)
{
    extern __shared__ __align__(16) uint32_t smem[];
    const int tid = threadIdx.x, wid = tid >> 5, lane = tid & 31;
    const int g = lane >> 2, tg = lane & 3;
    const int z = blockIdx.z;
    const __half* A = (z == 0) ? A0 : (z == 1) ? A1 : A2;
    const float*  R = (z == 0) ? R0 : (z == 1) ? R1 : R2;
    float*        C = (z == 0) ? C0 : (z == 1) ? C1 : C2;
    __half*      Ch = (z == 0) ? Ch0 : (z == 1) ? Ch1 : Ch2;
    const int m0 = blockIdx.y * 128;
    const int n0 = blockIdx.x * 128;
    const int moff = (wid & 3) * 32;
    const int noff = (wid >> 2) * 64;
    const __half* Ag = A + (size_t)m0 * KDIM;
    const __half* Bg = W + (size_t)n0 * KDIM;

    const uint32_t sbase = smem_u32(smem);

    // ldmatrix per-lane addressing: row-in-group + k-half select
    const int lrow8 = ((lane >> 3) & 1) * 8 + (lane & 7);
    const int lk4   = (lane >> 4) * 4;          // word offset: 0 or 4
    uint32_t aoff[2], boff[4];
    #pragma unroll
    for (int mt = 0; mt < 2; mt++)
        aoff[mt] = ((moff + mt * 16 + lrow8) * SMS + lk4) * 4;
    #pragma unroll
    for (int ntp = 0; ntp < 4; ntp++)
        boff[ntp] = ((noff + ntp * 16 + lrow8) * SMS + lk4) * 4;

    float acc[2][8][4];
    #pragma unroll
    for (int mt = 0; mt < 2; mt++)
        #pragma unroll
        for (int nt = 0; nt < 8; nt++)
            #pragma unroll
            for (int q = 0; q < 4; q++) acc[mt][nt][q] = 0.f;

    #define FILL_STAGE(stg, k0)                                                      \
    do {                                                                             \
        const uint32_t wA = sbase + (stg) * STG_BYTES;                               \
        const uint32_t wB = wA + SA_WORDS * 4;                                       \
        _Pragma("unroll")                                                            \
        for (int p = 0; p < 2; p++) {                                                \
            const int c = tid + 256 * p;                                             \
            const int row = c >> 2;                                                  \
            CP_ASYNC16(wA + (row * SMS + (c & 3) * 4) * 4,                           \
                       &Ag[(size_t)row * KDIM + (k0) + (c & 3) * 8]);                \
            CP_ASYNC16(wB + (row * SMS + (c & 3) * 4) * 4,                           \
                       &Bg[(size_t)row * KDIM + (k0) + (c & 3) * 8]);                \
        }                                                                            \
    } while (0)

    FILL_STAGE(0, 0);  CP_COMMIT();
    FILL_STAGE(1, KT); CP_COMMIT();
    CP_WAIT1();
    __syncthreads();

    for (int t = 0; t < NKT; t++) {
        if (t + 2 < NKT) { FILL_STAGE((t + 2) % 3, (t + 2) * KT); }
        CP_COMMIT();
        CP_WAIT2();
        __syncthreads();

        const uint32_t Ab = sbase + (t % 3) * STG_BYTES;
        const uint32_t Bb = Ab + SA_WORDS * 4;

        #pragma unroll
        for (int ks = 0; ks < 2; ks++) {
            const uint32_t kb4 = ks * 32;     // k16 half: 8 words = 32 bytes
            uint32_t af[2][4], bf[8][2];
            #pragma unroll
            for (int mt = 0; mt < 2; mt++)
                LDSM4(af[mt][0], af[mt][1], af[mt][2], af[mt][3], Ab + aoff[mt] + kb4);
            #pragma unroll
            for (int ntp = 0; ntp < 4; ntp++)
                LDSM4(bf[2*ntp][0], bf[2*ntp+1][0], bf[2*ntp][1], bf[2*ntp+1][1],
                      Bb + boff[ntp] + kb4);
            #pragma unroll
            for (int mt = 0; mt < 2; mt++)
                #pragma unroll
                for (int nt = 0; nt < 8; nt++) {
                    asm volatile(
                        "mma.sync.aligned.m16n8k16.row.col.f32.f16.f16.f32 "
                        "{%0,%1,%2,%3}, {%4,%5,%6,%7}, {%8,%9}, {%0,%1,%2,%3};"
                        : "+f"(acc[mt][nt][0]), "+f"(acc[mt][nt][1]),
                          "+f"(acc[mt][nt][2]), "+f"(acc[mt][nt][3])
                        : "r"(af[mt][0]), "r"(af[mt][1]), "r"(af[mt][2]), "r"(af[mt][3]),
                          "r"(bf[nt][0]), "r"(bf[nt][1]));
                }
        }
        __syncthreads();
    }

    // ---- epilogue ----
    #pragma unroll
    for (int mt = 0; mt < 2; mt++) {
        #pragma unroll
        for (int nt = 0; nt < 8; nt++) {
            const int n = n0 + noff + nt * 8 + 2 * tg;
            const int ra = m0 + moff + mt * 16 + g;
            const int rb = ra + 8;
            float bx = bias[n], by = bias[n + 1];
            float2 v0 = make_float2(acc[mt][nt][0] + bx, acc[mt][nt][1] + by);
            float2 v1 = make_float2(acc[mt][nt][2] + bx, acc[mt][nt][3] + by);
            if (mode & 1) {
                v0.x = fmaxf(v0.x, 0.f); v0.y = fmaxf(v0.y, 0.f);
                v1.x = fmaxf(v1.x, 0.f); v1.y = fmaxf(v1.y, 0.f);
            }
            if (mode & 2) {
                float2 r0v = *(const float2*)&R[(size_t)ra * N + n];
                float2 r1v = *(const float2*)&R[(size_t)rb * N + n];
                v0.x += r0v.x; v0.y += r0v.y;
                v1.x += r1v.x; v1.y += r1v.y;
            }
            if (mode & 4) {
                *(float2*)&C[(size_t)ra * N + n] = v0;
                *(float2*)&C[(size_t)rb * N + n] = v1;
            }
            if (mode & 8) {
                __half2 h0 = __floats2half2_rn(v0.x, v0.y);
                __half2 h1 = __floats2half2_rn(v1.x, v1.y);
                *(__half2*)&Ch[(size_t)ra * N + n] = h0;
                *(__half2*)&Ch[(size_t)rb * N + n] = h1;
            }
        }
    }
}

// ---------------- three N=1 GEMVs on fp16 E: re_h, rr_r, re_t ------------------------
__global__ void gemv3h(const __half* __restrict__ Eh, const __half* __restrict__ Er,
                       const __half* __restrict__ Et,
                       const float* __restrict__ Wre, const float* __restrict__ bre,
                       const float* __restrict__ Wrr, const float* __restrict__ brr,
                       float* __restrict__ reh, float* __restrict__ rrr, float* __restrict__ ret)
{
    const int warp = (blockIdx.x * blockDim.x + threadIdx.x) >> 5;
    const int lane = threadIdx.x & 31;
    if (warp >= NB) return;
    const __half* eh = Eh + (size_t)warp * HD;
    const __half* er = Er + (size_t)warp * HD;
    const __half* et = Et + (size_t)warp * HD;
    float s1 = 0.f, s2 = 0.f, s3 = 0.f;
    #pragma unroll
    for (int k = lane * 8; k < HD; k += 256) {
        uint4 a = *(const uint4*)&eh[k];
        uint4 b = *(const uint4*)&er[k];
        uint4 c = *(const uint4*)&et[k];
        #pragma unroll
        for (int j = 0; j < 4; j++) {
            float2 ea = __half22float2(*(const __half2*)((const uint32_t*)&a + j));
            float2 eb = __half22float2(*(const __half2*)((const uint32_t*)&b + j));
            float2 ec = __half22float2(*(const __half2*)((const uint32_t*)&c + j));
            float2 wre = *(const float2*)&Wre[k + 2 * j];
            float2 wrr = *(const float2*)&Wrr[k + 2 * j];
            s1 = fmaf(ea.x, wre.x, fmaf(ea.y, wre.y, s1));
            s2 = fmaf(eb.x, wrr.x, fmaf(eb.y, wrr.y, s2));
            s3 = fmaf(ec.x, wre.x, fmaf(ec.y, wre.y, s3));
        }
    }
    #pragma unroll
    for (int o = 16; o > 0; o >>= 1) {
        s1 += __shfl_down_sync(0xffffffffu, s1, o);
        s2 += __shfl_down_sync(0xffffffffu, s2, o);
        s3 += __shfl_down_sync(0xffffffffu, s3, o);
    }
    if (lane == 0) {
        reh[warp] = s1 + bre[0];
        rrr[warp] = s2 + brr[0];
        ret[warp] = s3 + bre[0];
    }
}

// ---------------- theta transpose: out[c, b] = pi * tanh(in[b, c]) --------------------
__global__ void transpose_th(const float* __restrict__ in, float* __restrict__ out)
{
    __shared__ float tile[32][33];
    const int tx = threadIdx.x, ty = threadIdx.y;
    const int x = blockIdx.x * 32 + tx;
    const int y0 = blockIdx.y * 32;
    #pragma unroll
    for (int j = ty; j < 32; j += 8)
        tile[j][tx] = in[(size_t)(y0 + j) * NP + x];
    __syncthreads();
    const int c0 = blockIdx.x * 32;
    #pragma unroll
    for (int j = ty; j < 32; j += 8) {
        float v = tile[tx][j];
        out[(size_t)(c0 + j) * NB + y0 + tx] = PIF * fast_tanh(v);
    }
}

// ---------------- fused l2-norm + transpose: outT[c, b] = in[b, c]/||in[b,:]|| --------
__global__ __launch_bounds__(256)
void transnorm(const float* __restrict__ in, float* __restrict__ outT)
{
    __shared__ float tile[32][DV + 1];
    __shared__ float rnorm[32];
    const int tid = threadIdx.x, wid = tid >> 5, lane = tid & 31;
    const int y0 = blockIdx.x * 32;

    #pragma unroll 4
    for (int i = 0; i < 32; i++)
        tile[i][tid] = in[(size_t)(y0 + i) * DV + tid];
    __syncthreads();

    #pragma unroll
    for (int rr = 0; rr < 4; rr++) {
        const int row = wid * 4 + rr;
        float s = 0.f;
        #pragma unroll
        for (int c = lane; c < DV; c += 32) { float v = tile[row][c]; s = fmaf(v, v, s); }
        #pragma unroll
        for (int o = 16; o > 0; o >>= 1) s += __shfl_down_sync(0xffffffffu, s, o);
        if (lane == 0) rnorm[row] = 1.f / (sqrtf(s) + EPSF);
    }
    __syncthreads();

    #pragma unroll 4
    for (int i = 0; i < 32; i++) {
        const int idx = tid + 256 * i;
        const int c = idx >> 5, bl = idx & 31;
        outT[(size_t)c * NB + y0 + bl] = tile[bl][c] * rnorm[bl];
    }
}

// ---------------- fused rotation + slerp + score --------------------------------------
__global__ void rot_score(
    const float* __restrict__ uhT, const float* __restrict__ utT,
    const float* __restrict__ thT, float* __restrict__ urT,
    const float* __restrict__ sim,
    const float* __restrict__ reh, const float* __restrict__ rrr, const float* __restrict__ ret,
    const float* __restrict__ ga_rho, const float* __restrict__ gb_rho,
    const float* __restrict__ ga_phi, const float* __restrict__ gb_phi,
    float* __restrict__ out)
{
    const int b = blockIdx.x * blockDim.x + threadIdx.x;
    if (b >= NB) return;

    float cur = uhT[b];
    float u0w = 0.f;
    #pragma unroll 4
    for (int i = 0; i < 255; i++) {
        float s, c; __sincosf(thT[(size_t)i * NB + b], &s, &c);
        float nxt = uhT[(size_t)(i + 1) * NB + b];
        float wi = c * cur - s * nxt;
        urT[(size_t)i * NB + b] = wi;
        if (i == 0) u0w = wi;
        cur = s * cur + c * nxt;
    }
    {
        float s, c; __sincosf(thT[(size_t)255 * NB + b], &s, &c);
        float w255 = c * cur - s * u0w;
        float w0   = s * cur + c * u0w;
        urT[(size_t)255 * NB + b] = w255;
        urT[b] = w0;
    }

    float dhr = 0.f, dht = 0.f, drt = 0.f, ssq = 0.f;
    const float uh0 = uhT[b], ut0 = utT[b];
    cur = urT[b];
    float w0sav = 0.f;
    #pragma unroll 4
    for (int i = 0; i < 255; i++) {
        float s, c; __sincosf(thT[(size_t)(256 + i) * NB + b], &s, &c);
        float nxt = urT[(size_t)(i + 1) * NB + b];
        float wi = c * cur - s * nxt;
        cur = s * cur + c * nxt;
        if (i == 0) {
            w0sav = wi;
        } else {
            float uh = uhT[(size_t)i * NB + b];
            float ut = utT[(size_t)i * NB + b];
            ssq += wi * wi; dhr += wi * uh; drt += wi * ut; dht += uh * ut;
        }
    }
    float w255f, w0f;
    {
        float s, c; __sincosf(thT[(size_t)511 * NB + b], &s, &c);
        w255f = c * cur - s * w0sav;
        w0f   = s * cur + c * w0sav;
    }
    {
        float uh255 = uhT[(size_t)255 * NB + b], ut255 = utT[(size_t)255 * NB + b];
        ssq += w255f * w255f + w0f * w0f;
        dhr += w255f * uh255 + w0f * uh0;
        drt += w255f * ut255 + w0f * ut0;
        dht += uh255 * ut255 + uh0 * ut0;
    }

    float nr = sqrtf(ssq);
    float inv_rot = 1.f / (nr + EPSF);
    float dhr_n = dhr * inv_rot;
    float dotc = fminf(fmaxf(dhr_n, -1.f + EPSF), 1.f - EPSF);
    float omega = acosf(dotc);
    float sin_om = sinf(omega);
    float sv = sim[b];
    float grho = 1.f / (1.f + expf(-(ga_rho[0] * sv + gb_rho[0])));
    float gphi = 1.f / (1.f + expf(-(ga_phi[0] * sv + gb_phi[0])));
    float ca, cb;
    if (omega > DELTAF) {
        float iso = 1.f / (sin_om + EPSF);
        ca = sinf((1.f - gphi) * omega) * iso;
        cb = sinf(gphi * omega) * iso;
    } else {
        ca = 1.f - gphi; cb = gphi;
    }
    float nrn = nr * inv_rot;
    float np2 = ca * ca + cb * cb * nrn * nrn + 2.f * ca * cb * dhr_n;
    float npv = sqrtf(fmaxf(np2, 0.f));
    float inv_np = 1.f / (npv + EPSF);
    float dpt = (ca * dht + cb * drt * inv_rot) * inv_np;

    float rho_h = fminf(softplusf(reh[b]), RHO_MAXF);
    float rho_p = fminf(fmaxf(rho_h + rrr[b] * grho, 0.f), RHO_MAXF);
    float rho_t = fminf(softplusf(ret[b]), RHO_MAXF);
    out[b] = -coshf(rho_p) * coshf(rho_t) + sinhf(rho_p) * sinhf(rho_t) * dpt;
}

// ---------------- launch --------------------------------------------------------------
extern "C" void kernel_launch(void* const* d_in, const int* in_sizes, int n_in,
                              void* d_out, int out_size)
{
    const float* ent  = (const float*)d_in[0];
    const float* rel  = (const float*)d_in[1];
    const float* lab  = (const float*)d_in[2];
    const float* sim  = (const float*)d_in[3];
    const float* Wv   = (const float*)d_in[4];
    const float* bv   = (const float*)d_in[5];
    const float* Wre  = (const float*)d_in[6];
    const float* bre  = (const float*)d_in[7];
    const float* Wrr  = (const float*)d_in[8];
    const float* brr  = (const float*)d_in[9];
    const float* Wt   = (const float*)d_in[10];
    const float* bt   = (const float*)d_in[11];
    const float* ga_rho = (const float*)d_in[12];
    const float* gb_rho = (const float*)d_in[13];
    const float* ga_phi = (const float*)d_in[14];
    const float* gb_phi = (const float*)d_in[15];
    const float* W1   = (const float*)d_in[16];
    const float* b1   = (const float*)d_in[17];
    const float* W2   = (const float*)d_in[18];
    const float* b2   = (const float*)d_in[19];
    float* out = (float*)d_out;

    __half *hEnt, *hRel, *hLab, *hH0, *hH1, *hH2, *hEh, *hEr, *hEt;
    __half *hW1, *hW2, *hWv, *hWt;
    float *Vh, *Vt, *TH, *thT, *uhT, *utT, *urT, *reh, *rrr, *ret;
    cudaGetSymbolAddress((void**)&hEnt, g_hEnt);
    cudaGetSymbolAddress((void**)&hRel, g_hRel);
    cudaGetSymbolAddress((void**)&hLab, g_hLab);
    cudaGetSymbolAddress((void**)&hH0,  g_hH0);
    cudaGetSymbolAddress((void**)&hH1,  g_hH1);
    cudaGetSymbolAddress((void**)&hH2,  g_hH2);
    cudaGetSymbolAddress((void**)&hEh,  g_hEh);
    cudaGetSymbolAddress((void**)&hEr,  g_hEr);
    cudaGetSymbolAddress((void**)&hEt,  g_hEt);
    cudaGetSymbolAddress((void**)&hW1,  g_hW1);
    cudaGetSymbolAddress((void**)&hW2,  g_hW2);
    cudaGetSymbolAddress((void**)&hWv,  g_hWv);
    cudaGetSymbolAddress((void**)&hWt,  g_hWt);
    cudaGetSymbolAddress((void**)&Vh,   g_Vh);
    cudaGetSymbolAddress((void**)&Vt,   g_Vt);
    cudaGetSymbolAddress((void**)&TH,   g_TH);
    cudaGetSymbolAddress((void**)&thT,  g_thT);
    cudaGetSymbolAddress((void**)&uhT,  g_uhT);
    cudaGetSymbolAddress((void**)&utT,  g_utT);
    cudaGetSymbolAddress((void**)&urT,  g_urT);
    cudaGetSymbolAddress((void**)&reh,  g_reh);
    cudaGetSymbolAddress((void**)&rrr,  g_rrr);
    cudaGetSymbolAddress((void**)&ret,  g_ret);

    cudaFuncSetAttribute(gemm_h, cudaFuncAttributeMaxDynamicSharedMemorySize,
                         GEMM_SMEM_BYTES);

    // fp32 -> fp16 conversions (inputs batched + weights)
    const int BIG = NB * HD;
    cvt3_f2h<<<dim3(BIG / (256 * 8), 3), 256>>>(ent, rel, lab, hEnt, hRel, hLab);
    cvt_f2h<<<(HD * HD) / (256 * 8), 256>>>(W1, hW1, HD * HD);
    cvt_f2h<<<(HD * HD) / (256 * 8), 256>>>(W2, hW2, HD * HD);
    cvt_f2h<<<(DV * HD) / (256 * 8), 256>>>(Wv, hWv, DV * HD);
    cvt_f2h<<<(NP * HD) / (256 * 8), 256>>>(Wt, hWt, NP * HD);

    const dim3 blk(256);
    // layer 1: hH_z = fp16(relu(X_z @ W1^T + b1))         mode 1|8 = 9
    gemm_h<<<dim3(HD/128, NB/128, 3), blk, GEMM_SMEM_BYTES>>>(
        hEnt, hRel, hLab, hW1, b1, nullptr, nullptr, nullptr,
        nullptr, nullptr, nullptr, hH0, hH1, hH2, HD, 9);
    // layer 2: hE_z = fp16(H_z @ W2^T + b2 + X_z)         mode 2|8 = 10 (no fp32 store)
    gemm_h<<<dim3(HD/128, NB/128, 3), blk, GEMM_SMEM_BYTES>>>(
        hH0, hH1, hH2, hW2, b2, ent, rel, lab,
        nullptr, nullptr, nullptr, hEh, hEr, hEt, HD, 10);
    // Wv projections (fp32 out)                           mode 4
    gemm_h<<<dim3(DV/128, NB/128, 2), blk, GEMM_SMEM_BYTES>>>(
        hEh, hEt, nullptr, hWv, bv, nullptr, nullptr, nullptr,
        Vh, Vt, nullptr, nullptr, nullptr, nullptr, DV, 4);
    // theta logits (fp32 out)                             mode 4
    gemm_h<<<dim3(NP/128, NB/128, 1), blk, GEMM_SMEM_BYTES>>>(
        hEr, nullptr, nullptr, hWt, bt, nullptr, nullptr, nullptr,
        TH, nullptr, nullptr, nullptr, nullptr, nullptr, NP, 4);

    // scalar GEMVs (rho logits / delta_rho) on fp16 E
    gemv3h<<<NB / 8, 256>>>(hEh, hEr, hEt, Wre, bre, Wrr, brr, reh, rrr, ret);

    // transposes: thetas (pi*tanh) + normalized u vectors
    transpose_th<<<dim3(NP / 32, NB / 32), dim3(32, 8)>>>(TH, thT);
    transnorm<<<NB / 32, 256>>>(Vh, uhT);
    transnorm<<<NB / 32, 256>>>(Vt, utT);

    // fused Givens sweeps + slerp + hyperbolic score
    rot_score<<<NB / 256, 256>>>(uhT, utT, thT, urT, sim, reh, rrr, ret,
                                 ga_rho, gb_rho, ga_phi, gb_phi, out);
    (void)in_sizes; (void)n_in; (void)out_size;
}